// round 14
// baseline (speedup 1.0000x reference)
#include <cuda_runtime.h>
#include <cstddef>
#include <cstdint>

#define NN 2048
#define DM 128
#define HH 8
#define DH 16
#define ED 8

#define BI 16
#define TJ 32
#define NSPLIT 16
#define JRANGE 128                    // per block, as 2 sub-ranges of 64
#define SUBR 64
#define JT_PER 2                      // tiles per sub-range
#define SCSTR 68                      // score row stride (floats, 16B-aligned rows)
#define VSTR4 65                      // VT row stride (float4 units)

// ---------- packed f32x2 helpers ----------
using u64 = unsigned long long;
__device__ __forceinline__ u64 f2_pack(float lo, float hi) {
    u64 r; asm("mov.b64 %0, {%1,%2};" : "=l"(r) : "f"(lo), "f"(hi)); return r;
}
__device__ __forceinline__ u64 f2_mul(u64 a, u64 b) {
    u64 d; asm("mul.rn.f32x2 %0, %1, %2;" : "=l"(d) : "l"(a), "l"(b)); return d;
}
__device__ __forceinline__ u64 f2_fma(u64 a, u64 b, u64 c) {
    u64 d; asm("fma.rn.f32x2 %0, %1, %2, %3;" : "=l"(d) : "l"(a), "l"(b), "l"(c)); return d;
}
__device__ __forceinline__ u64 f2_add(u64 a, u64 b) {
    u64 d; asm("add.rn.f32x2 %0, %1, %2;" : "=l"(d) : "l"(a), "l"(b)); return d;
}
__device__ __forceinline__ float f2_red(u64 a) {
    float lo, hi; asm("mov.b64 {%0,%1}, %2;" : "=f"(lo), "=f"(hi) : "l"(a)); return lo + hi;
}
__device__ __forceinline__ void f2_unpack(u64 a, float& lo, float& hi) {
    asm("mov.b64 {%0,%1}, %2;" : "=f"(lo), "=f"(hi) : "l"(a));
}

// ---------- device scratch ----------
__device__ float g_Q  [NN * DM];               // pre-scaled by 0.25
__device__ float g_KT [NN * DM];               // [h*4+dq][j][4]  (transposed K)
__device__ float g_VT [NN * DM];               // [h*4+dq][j][4]  (transposed V)
__device__ float g_QW [NN * HH * ED];          // pre-scaled by 0.25
__device__ float g_part[(size_t)NN * NSPLIT * DM];   // [i][split][128]
__device__ float g_lsum[NN * NSPLIT * HH];           // [i][split][8]

// ---------- kernel 1: projections (256 threads, 8 rows, grid 256; Wer folded in) ----------
#define PCH 16
__global__ __launch_bounds__(256)
void proj_kernel(const float* __restrict__ X,
                 const float* __restrict__ Wq,
                 const float* __restrict__ Wk,
                 const float* __restrict__ Wv,
                 const float* __restrict__ We,
                 const float* __restrict__ Wr) {
    __shared__ float xs[8][DM];
    __shared__ float qs[8][DM];
    __shared__ float ws[3][PCH][DM];
    __shared__ float wer_s[ED][DM];
    const int i0 = blockIdx.x * 8;
    const int tid = threadIdx.x;
    const int c = tid & 127;
    const int rg = tid >> 7;           // rows rg*4 .. rg*4+3

    // fold Wer = We @ Wr (each half computes 4 e-rows)
    #pragma unroll
    for (int e = rg * 4; e < rg * 4 + 4; e++) {
        float s = 0.f;
        #pragma unroll 8
        for (int k = 0; k < 32; k++) s += We[e * 32 + k] * Wr[k * DM + c];
        wer_s[e][c] = s;
    }

    if (rg == 0) {
        #pragma unroll
        for (int r = 0; r < 8; r++) xs[r][c] = X[(i0 + r) * DM + c];
    }

    float qa[4], ka[4], va[4];
    #pragma unroll
    for (int r = 0; r < 4; r++) { qa[r] = 0.f; ka[r] = 0.f; va[r] = 0.f; }

    for (int ch = 0; ch < DM / PCH; ch++) {
        const int d0 = ch * PCH;
        __syncthreads();
        #pragma unroll
        for (int s = 0; s < 6; s++) {
            int t = tid + s * 256;
            int m = t / (PCH * 32);
            int rem = t % (PCH * 32);
            int dd = rem >> 5, c4 = rem & 31;
            const float* Wm = (m == 0) ? Wq : (m == 1) ? Wk : Wv;
            *(float4*)&ws[m][dd][c4 * 4] = *(const float4*)&Wm[(d0 + dd) * DM + c4 * 4];
        }
        __syncthreads();
        #pragma unroll
        for (int dd = 0; dd < PCH; dd++) {
            float wq = ws[0][dd][c];
            float wk = ws[1][dd][c];
            float wv = ws[2][dd][c];
            #pragma unroll
            for (int r = 0; r < 4; r++) {
                float x = xs[rg * 4 + r][d0 + dd];
                qa[r] += x * wq;
                ka[r] += x * wk;
                va[r] += x * wv;
            }
        }
    }
    const int h = c >> 4, d = c & 15;
    const int dg = d >> 2, dl = d & 3;
    #pragma unroll
    for (int r = 0; r < 4; r++) {
        int i = i0 + rg * 4 + r;
        float q = qa[r] * 0.25f;               // fold 1/sqrt(dh)
        g_Q[i * DM + c] = q;
        qs[rg * 4 + r][c] = q;
        g_KT[(((h * 4 + dg) * NN) + i) * 4 + dl] = ka[r];
        g_VT[(((h * 4 + dg) * NN) + i) * 4 + dl] = va[r];
    }
    __syncthreads();
    if (c < 64) {
        const int hh = c >> 3, e = c & 7;
        #pragma unroll
        for (int r = 0; r < 4; r++) {
            float s = 0.f;
            #pragma unroll
            for (int dd = 0; dd < DH; dd++)
                s += qs[rg * 4 + r][hh * DH + dd] * wer_s[e][hh * DH + dd];
            g_QW[(i0 + rg * 4 + r) * 64 + c] = s;
        }
    }
}

// ---------- kernel 2: fused attention (256 threads, warp = head, 3 blocks/SM) ----------
__global__ __launch_bounds__(256, 3)
void attn_kernel(const int* __restrict__ adj, const float* __restrict__ edge) {
    extern __shared__ float sm[];
    float* sc = sm;                                  // [h][i][68]
    float* VT = sc + HH * BI * SCSTR;                // float4[h*4+dq][65]
    unsigned* adjm = (unsigned*)(VT + 32 * VSTR4 * 4);  // 32 words [i][tile]

    const int tid = threadIdx.x;
    const int i0 = blockIdx.x * BI;
    const int jbase = blockIdx.y * JRANGE;

    const int w = tid >> 5, lane = tid & 31;
    const int h = w;                                   // warp = head
    const int io = lane >> 2, dq = lane & 3;

    u64 acc[2][2] = {{0ull, 0ull}, {0ull, 0ull}};
    float lp[2] = {0.f, 0.f};

    const ulonglong2* KTg = (const ulonglong2*)g_KT;   // 16B rows [h*4+dg][NN]
    const float4*     VTg = (const float4*)g_VT;

    for (int sr = 0; sr < 2; sr++) {
        const int jb = jbase + sr * SUBR;
        if (sr) __syncthreads();   // previous phase-3 VT reads done before restage

        // ---- stage V tile (coalesced from transposed global) ----
        {
            float4* VT4 = (float4*)VT;
            #pragma unroll
            for (int s = 0; s < 8; s++) {
                int t4 = tid + s * 256;                 // 2048 total
                int hd = t4 >> 6, jj = t4 & 63;
                VT4[hd * VSTR4 + jj] = VTg[hd * NN + jb + jj];
            }
        }

        // ---- phase 1: edge biases (i = w, w+8; 2 tiles; MLP-4 prefetch) ----
        {
            ulonglong2 E01[4], E23[4];
            int av[4];
            #pragma unroll
            for (int q = 0; q < 4; q++) {
                int i = w + 8 * (q >> 1);
                int t = q & 1;
                const float* eb = edge +
                    ((size_t)(i0 + i) * NN + jb + t * TJ + lane) * ED;
                E01[q] = *(const ulonglong2*)eb;
                E23[q] = *(const ulonglong2*)(eb + 4);
                av[q] = adj[(size_t)(i0 + i) * NN + jb + t * TJ + lane];
            }
            #pragma unroll
            for (int q = 0; q < 4; q++) {
                int i = w + 8 * (q >> 1);
                int t = q & 1;
                unsigned msk = __ballot_sync(0xffffffffu, av[q] != 0);
                if (lane == 0) adjm[i * JT_PER + t] = msk;
                const ulonglong2* qwp = (const ulonglong2*)(g_QW + (i0 + i) * 64);
                #pragma unroll
                for (int hh = 0; hh < 8; hh++) {
                    ulonglong2 w01 = qwp[hh * 2];
                    ulonglong2 w23 = qwp[hh * 2 + 1];
                    u64 t0 = f2_mul(w01.x, E01[q].x);
                    u64 t1 = f2_mul(w01.y, E01[q].y);
                    t0 = f2_fma(w23.x, E23[q].x, t0);
                    t1 = f2_fma(w23.y, E23[q].y, t1);
                    sc[(hh * BI + i) * SCSTR + t * TJ + lane] = f2_red(f2_add(t0, t1));
                }
            }
        }
        __syncthreads();   // sc biases + adjm + VT ready

        // ---- phase 2: both tiles fused; K from gmem (coalesced), Q broadcast gmem ----
        {
            ulonglong2 ka0 = KTg[(h * 4 + 0) * NN + jb + lane];        // tile 0
            ulonglong2 ka1 = KTg[(h * 4 + 1) * NN + jb + lane];
            ulonglong2 ka2 = KTg[(h * 4 + 2) * NN + jb + lane];
            ulonglong2 ka3 = KTg[(h * 4 + 3) * NN + jb + lane];
            ulonglong2 kb0 = KTg[(h * 4 + 0) * NN + jb + TJ + lane];   // tile 1
            ulonglong2 kb1 = KTg[(h * 4 + 1) * NN + jb + TJ + lane];
            ulonglong2 kb2 = KTg[(h * 4 + 2) * NN + jb + TJ + lane];
            ulonglong2 kb3 = KTg[(h * 4 + 3) * NN + jb + TJ + lane];
            #pragma unroll
            for (int ii = 0; ii < BI; ii++) {
                const ulonglong2* qp = (const ulonglong2*)(g_Q + (i0 + ii) * DM + h * DH);
                ulonglong2 q0 = qp[0], q1 = qp[1], q2 = qp[2], q3 = qp[3];
                u64 a0 = f2_mul(q0.x, ka0.x);
                u64 a1 = f2_mul(q0.y, ka0.y);
                u64 b0 = f2_mul(q0.x, kb0.x);
                u64 b1 = f2_mul(q0.y, kb0.y);
                a0 = f2_fma(q1.x, ka1.x, a0);
                a1 = f2_fma(q1.y, ka1.y, a1);
                b0 = f2_fma(q1.x, kb1.x, b0);
                b1 = f2_fma(q1.y, kb1.y, b1);
                a0 = f2_fma(q2.x, ka2.x, a0);
                a1 = f2_fma(q2.y, ka2.y, a1);
                b0 = f2_fma(q2.x, kb2.x, b0);
                b1 = f2_fma(q2.y, kb2.y, b1);
                a0 = f2_fma(q3.x, ka3.x, a0);
                a1 = f2_fma(q3.y, ka3.y, a1);
                b0 = f2_fma(q3.x, kb3.x, b0);
                b1 = f2_fma(q3.y, kb3.y, b1);
                float sA = f2_red(f2_add(a0, a1));
                float sB = f2_red(f2_add(b0, b1));
                int idx = (h * BI + ii) * SCSTR + lane;
                sA = sA + sc[idx];
                sB = sB + sc[idx + TJ];
                sA = fmaxf(sA, 0.2f * sA);
                sB = fmaxf(sB, 0.2f * sB);
                unsigned mA = adjm[ii * JT_PER + 0];
                unsigned mB = adjm[ii * JT_PER + 1];
                float pA = ((mA >> lane) & 1u) ? __expf(sA) : 0.f;
                float pB = ((mB >> lane) & 1u) ? __expf(sB) : 0.f;
                sc[idx] = pA;
                sc[idx + TJ] = pB;
            }
        }
        __syncwarp();

        // ---- phase 3: PV; float4 p reads, V from smem, both octets share V ----
        #pragma unroll
        for (int t = 0; t < JT_PER; t++) {
            const float* pb0 = &sc[(h * BI + io) * SCSTR + t * TJ];
            const float* pb1 = &sc[(h * BI + 8 + io) * SCSTR + t * TJ];
            const ulonglong2* vb =
                (const ulonglong2*)VT + (h * 4 + dq) * VSTR4 + t * TJ;
            #pragma unroll
            for (int j4 = 0; j4 < TJ / 4; j4++) {
                float4 PA = *(const float4*)(pb0 + j4 * 4);
                float4 PB = *(const float4*)(pb1 + j4 * 4);
                ulonglong2 v0 = vb[j4 * 4 + 0];
                ulonglong2 v1 = vb[j4 * 4 + 1];
                ulonglong2 v2 = vb[j4 * 4 + 2];
                ulonglong2 v3 = vb[j4 * 4 + 3];
                u64 a0 = f2_pack(PA.x, PA.x), a1 = f2_pack(PA.y, PA.y);
                u64 a2 = f2_pack(PA.z, PA.z), a3 = f2_pack(PA.w, PA.w);
                u64 b0 = f2_pack(PB.x, PB.x), b1 = f2_pack(PB.y, PB.y);
                u64 b2 = f2_pack(PB.z, PB.z), b3 = f2_pack(PB.w, PB.w);
                acc[0][0] = f2_fma(a0, v0.x, acc[0][0]);
                acc[0][1] = f2_fma(a0, v0.y, acc[0][1]);
                acc[1][0] = f2_fma(b0, v0.x, acc[1][0]);
                acc[1][1] = f2_fma(b0, v0.y, acc[1][1]);
                acc[0][0] = f2_fma(a1, v1.x, acc[0][0]);
                acc[0][1] = f2_fma(a1, v1.y, acc[0][1]);
                acc[1][0] = f2_fma(b1, v1.x, acc[1][0]);
                acc[1][1] = f2_fma(b1, v1.y, acc[1][1]);
                acc[0][0] = f2_fma(a2, v2.x, acc[0][0]);
                acc[0][1] = f2_fma(a2, v2.y, acc[0][1]);
                acc[1][0] = f2_fma(b2, v2.x, acc[1][0]);
                acc[1][1] = f2_fma(b2, v2.y, acc[1][1]);
                acc[0][0] = f2_fma(a3, v3.x, acc[0][0]);
                acc[0][1] = f2_fma(a3, v3.y, acc[0][1]);
                acc[1][0] = f2_fma(b3, v3.x, acc[1][0]);
                acc[1][1] = f2_fma(b3, v3.y, acc[1][1]);
                lp[0] += (PA.x + PA.y) + (PA.z + PA.w);
                lp[1] += (PB.x + PB.y) + (PB.z + PB.w);
            }
        }
        __syncwarp();
    }

    // ---- direct store ----
    #pragma unroll
    for (int oct = 0; oct < 2; oct++) {
        const int i = oct * 8 + io;
        float a0, a1, a2, a3;
        f2_unpack(acc[oct][0], a0, a1);
        f2_unpack(acc[oct][1], a2, a3);
        *(float4*)&g_part[((size_t)(i0 + i) * NSPLIT + blockIdx.y) * DM + h * DH + dq * 4] =
            make_float4(a0, a1, a2, a3);
        if (dq == 0)
            g_lsum[((i0 + i) * NSPLIT + blockIdx.y) * HH + h] = lp[oct];
    }
}

// ---------- kernel 3: combine partials + normalize + @ Wo (256 thr, 4 rows, grid 512) ----------
__global__ __launch_bounds__(256)
void combine_kernel(const float* __restrict__ Wo, float* __restrict__ out) {
    __shared__ float xs[4][DM];
    __shared__ float ws[PCH][DM];
    const int i0 = blockIdx.x * 4;
    const int tid = threadIdx.x;
    const int c = tid & 127;
    const int rh = tid >> 7;           // rows {0,1} or {2,3}
    const int h = c >> 4;
    #pragma unroll
    for (int r = 0; r < 2; r++) {
        int i = i0 + rh * 2 + r;
        float s = 0.f, l = 0.f;
        #pragma unroll
        for (int sp = 0; sp < NSPLIT; sp++) {
            s += g_part[((size_t)i * NSPLIT + sp) * DM + c];
            l += g_lsum[(i * NSPLIT + sp) * HH + h];
        }
        xs[rh * 2 + r][c] = s / l;
    }
    float a[2] = {0.f, 0.f};
    for (int ch = 0; ch < DM / PCH; ch++) {
        const int d0 = ch * PCH;
        __syncthreads();
        #pragma unroll
        for (int s = 0; s < 2; s++) {
            int t = tid + s * 256;
            int dd = t >> 5, c4 = t & 31;
            *(float4*)&ws[dd][c4 * 4] = *(const float4*)&Wo[(d0 + dd) * DM + c4 * 4];
        }
        __syncthreads();
        #pragma unroll
        for (int dd = 0; dd < PCH; dd++) {
            float wv = ws[dd][c];
            a[0] += xs[rh * 2 + 0][d0 + dd] * wv;
            a[1] += xs[rh * 2 + 1][d0 + dd] * wv;
        }
    }
    out[(i0 + rh * 2 + 0) * DM + c] = a[0];
    out[(i0 + rh * 2 + 1) * DM + c] = a[1];
}

// ---------- launch ----------
extern "C" void kernel_launch(void* const* d_in, const int* in_sizes, int n_in,
                              void* d_out, int out_size) {
    const float* X    = (const float*)d_in[0];
    const int*   adj  = (const int*)  d_in[1];
    const float* edge = (const float*)d_in[2];
    const float* Wq   = (const float*)d_in[3];
    const float* Wk   = (const float*)d_in[4];
    const float* Wv   = (const float*)d_in[5];
    const float* We   = (const float*)d_in[6];
    const float* Wr   = (const float*)d_in[7];
    const float* Wo   = (const float*)d_in[8];
    float* out = (float*)d_out;

    const int smem_bytes = (HH*BI*SCSTR + 32*VSTR4*4 + BI*JT_PER) * 4;
    cudaFuncSetAttribute(attn_kernel, cudaFuncAttributeMaxDynamicSharedMemorySize, smem_bytes);

    proj_kernel<<<NN / 8, 256>>>(X, Wq, Wk, Wv, We, Wr);
    attn_kernel<<<dim3(NN / BI, NSPLIT), 256, smem_bytes>>>(adj, edge);
    combine_kernel<<<NN / 4, 256>>>(Wo, out);
}

// round 15
// speedup vs baseline: 1.0451x; 1.0451x over previous
#include <cuda_runtime.h>
#include <cstddef>
#include <cstdint>

#define NN 2048
#define DM 128
#define HH 8
#define DH 16
#define ED 8

#define BI 16
#define TJ 32
#define NSPLIT 16
#define JRANGE 128                    // per block, as 2 sub-ranges of 64
#define SUBR 64
#define JT_PER 2                      // tiles per sub-range
#define SCSTR 68                      // score row stride (floats, 16B-aligned rows)
#define VSTR4 65                      // VT row stride (float4 units)

// ---------- packed f32x2 helpers ----------
using u64 = unsigned long long;
__device__ __forceinline__ u64 f2_pack(float lo, float hi) {
    u64 r; asm("mov.b64 %0, {%1,%2};" : "=l"(r) : "f"(lo), "f"(hi)); return r;
}
__device__ __forceinline__ u64 f2_mul(u64 a, u64 b) {
    u64 d; asm("mul.rn.f32x2 %0, %1, %2;" : "=l"(d) : "l"(a), "l"(b)); return d;
}
__device__ __forceinline__ u64 f2_fma(u64 a, u64 b, u64 c) {
    u64 d; asm("fma.rn.f32x2 %0, %1, %2, %3;" : "=l"(d) : "l"(a), "l"(b), "l"(c)); return d;
}
__device__ __forceinline__ u64 f2_add(u64 a, u64 b) {
    u64 d; asm("add.rn.f32x2 %0, %1, %2;" : "=l"(d) : "l"(a), "l"(b)); return d;
}
__device__ __forceinline__ float f2_red(u64 a) {
    float lo, hi; asm("mov.b64 {%0,%1}, %2;" : "=f"(lo), "=f"(hi) : "l"(a)); return lo + hi;
}
__device__ __forceinline__ void f2_unpack(u64 a, float& lo, float& hi) {
    asm("mov.b64 {%0,%1}, %2;" : "=f"(lo), "=f"(hi) : "l"(a));
}

// ---------- device scratch ----------
__device__ float g_Q  [NN * DM];               // pre-scaled by 0.25
__device__ float g_KT [NN * DM];               // [h*4+dq][j][4]  (transposed K)
__device__ float g_VT [NN * DM];               // [h*4+dq][j][4]  (transposed V)
__device__ float g_QW [NN * HH * ED];          // pre-scaled by 0.25
__device__ float g_part[(size_t)NN * NSPLIT * DM];   // [i][split][128]
__device__ float g_lsum[NN * NSPLIT * HH];           // [i][split][8]

// ---------- kernel 1: projections (512 threads, 16 rows, grid 128, dbl-buffered) ----------
#define PCH 16
__global__ __launch_bounds__(512)
void proj_kernel(const float* __restrict__ X,
                 const float* __restrict__ Wq,
                 const float* __restrict__ Wk,
                 const float* __restrict__ Wv,
                 const float* __restrict__ We,
                 const float* __restrict__ Wr) {
    __shared__ float xs[16][DM];
    __shared__ float qs[16][DM];
    __shared__ float ws[2][3][PCH][DM];      // double-buffered weight chunks
    __shared__ float wer_s[ED][DM];
    const int i0 = blockIdx.x * 16;
    const int tid = threadIdx.x;
    const int c = tid & 127;
    const int rg = tid >> 7;                 // 0..3: rows rg*4 .. rg*4+3

    // fold Wer = We @ Wr (each quarter computes 2 e-rows)
    #pragma unroll
    for (int e = rg * 2; e < rg * 2 + 2; e++) {
        float s = 0.f;
        #pragma unroll 8
        for (int k = 0; k < 32; k++) s += We[e * 32 + k] * Wr[k * DM + c];
        wer_s[e][c] = s;
    }

    #pragma unroll
    for (int k = 0; k < 4; k++) xs[rg * 4 + k][c] = X[(i0 + rg * 4 + k) * DM + c];

    // stage chunk 0 into buffer 0 (1536 float4 / 512 threads = 3 each)
    #pragma unroll
    for (int s = 0; s < 3; s++) {
        int t = tid + s * 512;
        int m = t / (PCH * 32);
        int rem = t % (PCH * 32);
        int dd = rem >> 5, c4 = rem & 31;
        const float* Wm = (m == 0) ? Wq : (m == 1) ? Wk : Wv;
        *(float4*)&ws[0][m][dd][c4 * 4] = *(const float4*)&Wm[dd * DM + c4 * 4];
    }
    __syncthreads();

    float qa[4], ka[4], va[4];
    #pragma unroll
    for (int r = 0; r < 4; r++) { qa[r] = 0.f; ka[r] = 0.f; va[r] = 0.f; }

    #pragma unroll
    for (int ch = 0; ch < DM / PCH; ch++) {
        const int buf = ch & 1;
        // prefetch next chunk into the other buffer (overlaps with MACs below)
        if (ch + 1 < DM / PCH) {
            const int d0n = (ch + 1) * PCH;
            #pragma unroll
            for (int s = 0; s < 3; s++) {
                int t = tid + s * 512;
                int m = t / (PCH * 32);
                int rem = t % (PCH * 32);
                int dd = rem >> 5, c4 = rem & 31;
                const float* Wm = (m == 0) ? Wq : (m == 1) ? Wk : Wv;
                *(float4*)&ws[buf ^ 1][m][dd][c4 * 4] =
                    *(const float4*)&Wm[(d0n + dd) * DM + c4 * 4];
            }
        }
        const int d0 = ch * PCH;
        #pragma unroll
        for (int dd = 0; dd < PCH; dd++) {
            float wq = ws[buf][0][dd][c];
            float wk = ws[buf][1][dd][c];
            float wv = ws[buf][2][dd][c];
            #pragma unroll
            for (int r = 0; r < 4; r++) {
                float x = xs[rg * 4 + r][d0 + dd];
                qa[r] += x * wq;
                ka[r] += x * wk;
                va[r] += x * wv;
            }
        }
        __syncthreads();   // buffer (buf) free for restaging; (buf^1) stores visible
    }
    const int h = c >> 4, d = c & 15;
    const int dg = d >> 2, dl = d & 3;
    #pragma unroll
    for (int r = 0; r < 4; r++) {
        int i = i0 + rg * 4 + r;
        float q = qa[r] * 0.25f;               // fold 1/sqrt(dh)
        g_Q[i * DM + c] = q;
        qs[rg * 4 + r][c] = q;
        g_KT[(((h * 4 + dg) * NN) + i) * 4 + dl] = ka[r];
        g_VT[(((h * 4 + dg) * NN) + i) * 4 + dl] = va[r];
    }
    __syncthreads();
    if (c < 64) {
        const int hh = c >> 3, e = c & 7;
        #pragma unroll
        for (int r = 0; r < 4; r++) {
            float s = 0.f;
            #pragma unroll
            for (int dd = 0; dd < DH; dd++)
                s += qs[rg * 4 + r][hh * DH + dd] * wer_s[e][hh * DH + dd];
            g_QW[(i0 + rg * 4 + r) * 64 + c] = s;
        }
    }
}

// ---------- kernel 2: fused attention (256 threads, warp = head, 3 blocks/SM) ----------
__global__ __launch_bounds__(256, 3)
void attn_kernel(const int* __restrict__ adj, const float* __restrict__ edge) {
    extern __shared__ float sm[];
    float* sc = sm;                                  // [h][i][68]
    float* VT = sc + HH * BI * SCSTR;                // float4[h*4+dq][65]
    unsigned* adjm = (unsigned*)(VT + 32 * VSTR4 * 4);  // 32 words [i][tile]

    const int tid = threadIdx.x;
    const int i0 = blockIdx.x * BI;
    const int jbase = blockIdx.y * JRANGE;

    const int w = tid >> 5, lane = tid & 31;
    const int h = w;                                   // warp = head
    const int io = lane >> 2, dq = lane & 3;

    u64 acc[2][2] = {{0ull, 0ull}, {0ull, 0ull}};
    float lp[2] = {0.f, 0.f};

    const ulonglong2* KTg = (const ulonglong2*)g_KT;   // 16B rows [h*4+dg][NN]
    const float4*     VTg = (const float4*)g_VT;

    for (int sr = 0; sr < 2; sr++) {
        const int jb = jbase + sr * SUBR;
        if (sr) __syncthreads();   // previous phase-3 VT reads done before restage

        // ---- stage V tile (coalesced from transposed global) ----
        {
            float4* VT4 = (float4*)VT;
            #pragma unroll
            for (int s = 0; s < 8; s++) {
                int t4 = tid + s * 256;                 // 2048 total
                int hd = t4 >> 6, jj = t4 & 63;
                VT4[hd * VSTR4 + jj] = VTg[hd * NN + jb + jj];
            }
        }

        // ---- phase 1: edge biases (i = w, w+8; 2 tiles; MLP-4 prefetch) ----
        {
            ulonglong2 E01[4], E23[4];
            int av[4];
            #pragma unroll
            for (int q = 0; q < 4; q++) {
                int i = w + 8 * (q >> 1);
                int t = q & 1;
                const float* eb = edge +
                    ((size_t)(i0 + i) * NN + jb + t * TJ + lane) * ED;
                E01[q] = *(const ulonglong2*)eb;
                E23[q] = *(const ulonglong2*)(eb + 4);
                av[q] = adj[(size_t)(i0 + i) * NN + jb + t * TJ + lane];
            }
            #pragma unroll
            for (int q = 0; q < 4; q++) {
                int i = w + 8 * (q >> 1);
                int t = q & 1;
                unsigned msk = __ballot_sync(0xffffffffu, av[q] != 0);
                if (lane == 0) adjm[i * JT_PER + t] = msk;
                const ulonglong2* qwp = (const ulonglong2*)(g_QW + (i0 + i) * 64);
                #pragma unroll
                for (int hh = 0; hh < 8; hh++) {
                    ulonglong2 w01 = qwp[hh * 2];
                    ulonglong2 w23 = qwp[hh * 2 + 1];
                    u64 t0 = f2_mul(w01.x, E01[q].x);
                    u64 t1 = f2_mul(w01.y, E01[q].y);
                    t0 = f2_fma(w23.x, E23[q].x, t0);
                    t1 = f2_fma(w23.y, E23[q].y, t1);
                    sc[(hh * BI + i) * SCSTR + t * TJ + lane] = f2_red(f2_add(t0, t1));
                }
            }
        }
        __syncthreads();   // sc biases + adjm + VT ready

        // ---- phase 2: both tiles fused; K from gmem (coalesced), Q broadcast gmem ----
        {
            ulonglong2 ka0 = KTg[(h * 4 + 0) * NN + jb + lane];        // tile 0
            ulonglong2 ka1 = KTg[(h * 4 + 1) * NN + jb + lane];
            ulonglong2 ka2 = KTg[(h * 4 + 2) * NN + jb + lane];
            ulonglong2 ka3 = KTg[(h * 4 + 3) * NN + jb + lane];
            ulonglong2 kb0 = KTg[(h * 4 + 0) * NN + jb + TJ + lane];   // tile 1
            ulonglong2 kb1 = KTg[(h * 4 + 1) * NN + jb + TJ + lane];
            ulonglong2 kb2 = KTg[(h * 4 + 2) * NN + jb + TJ + lane];
            ulonglong2 kb3 = KTg[(h * 4 + 3) * NN + jb + TJ + lane];
            #pragma unroll
            for (int ii = 0; ii < BI; ii++) {
                const ulonglong2* qp = (const ulonglong2*)(g_Q + (i0 + ii) * DM + h * DH);
                ulonglong2 q0 = qp[0], q1 = qp[1], q2 = qp[2], q3 = qp[3];
                u64 a0 = f2_mul(q0.x, ka0.x);
                u64 a1 = f2_mul(q0.y, ka0.y);
                u64 b0 = f2_mul(q0.x, kb0.x);
                u64 b1 = f2_mul(q0.y, kb0.y);
                a0 = f2_fma(q1.x, ka1.x, a0);
                a1 = f2_fma(q1.y, ka1.y, a1);
                b0 = f2_fma(q1.x, kb1.x, b0);
                b1 = f2_fma(q1.y, kb1.y, b1);
                a0 = f2_fma(q2.x, ka2.x, a0);
                a1 = f2_fma(q2.y, ka2.y, a1);
                b0 = f2_fma(q2.x, kb2.x, b0);
                b1 = f2_fma(q2.y, kb2.y, b1);
                a0 = f2_fma(q3.x, ka3.x, a0);
                a1 = f2_fma(q3.y, ka3.y, a1);
                b0 = f2_fma(q3.x, kb3.x, b0);
                b1 = f2_fma(q3.y, kb3.y, b1);
                float sA = f2_red(f2_add(a0, a1));
                float sB = f2_red(f2_add(b0, b1));
                int idx = (h * BI + ii) * SCSTR + lane;
                sA = sA + sc[idx];
                sB = sB + sc[idx + TJ];
                sA = fmaxf(sA, 0.2f * sA);
                sB = fmaxf(sB, 0.2f * sB);
                unsigned mA = adjm[ii * JT_PER + 0];
                unsigned mB = adjm[ii * JT_PER + 1];
                float pA = ((mA >> lane) & 1u) ? __expf(sA) : 0.f;
                float pB = ((mB >> lane) & 1u) ? __expf(sB) : 0.f;
                sc[idx] = pA;
                sc[idx + TJ] = pB;
            }
        }
        __syncwarp();

        // ---- phase 3: PV; float4 p reads, V from smem, both octets share V ----
        #pragma unroll
        for (int t = 0; t < JT_PER; t++) {
            const float* pb0 = &sc[(h * BI + io) * SCSTR + t * TJ];
            const float* pb1 = &sc[(h * BI + 8 + io) * SCSTR + t * TJ];
            const ulonglong2* vb =
                (const ulonglong2*)VT + (h * 4 + dq) * VSTR4 + t * TJ;
            #pragma unroll
            for (int j4 = 0; j4 < TJ / 4; j4++) {
                float4 PA = *(const float4*)(pb0 + j4 * 4);
                float4 PB = *(const float4*)(pb1 + j4 * 4);
                ulonglong2 v0 = vb[j4 * 4 + 0];
                ulonglong2 v1 = vb[j4 * 4 + 1];
                ulonglong2 v2 = vb[j4 * 4 + 2];
                ulonglong2 v3 = vb[j4 * 4 + 3];
                u64 a0 = f2_pack(PA.x, PA.x), a1 = f2_pack(PA.y, PA.y);
                u64 a2 = f2_pack(PA.z, PA.z), a3 = f2_pack(PA.w, PA.w);
                u64 b0 = f2_pack(PB.x, PB.x), b1 = f2_pack(PB.y, PB.y);
                u64 b2 = f2_pack(PB.z, PB.z), b3 = f2_pack(PB.w, PB.w);
                acc[0][0] = f2_fma(a0, v0.x, acc[0][0]);
                acc[0][1] = f2_fma(a0, v0.y, acc[0][1]);
                acc[1][0] = f2_fma(b0, v0.x, acc[1][0]);
                acc[1][1] = f2_fma(b0, v0.y, acc[1][1]);
                acc[0][0] = f2_fma(a1, v1.x, acc[0][0]);
                acc[0][1] = f2_fma(a1, v1.y, acc[0][1]);
                acc[1][0] = f2_fma(b1, v1.x, acc[1][0]);
                acc[1][1] = f2_fma(b1, v1.y, acc[1][1]);
                acc[0][0] = f2_fma(a2, v2.x, acc[0][0]);
                acc[0][1] = f2_fma(a2, v2.y, acc[0][1]);
                acc[1][0] = f2_fma(b2, v2.x, acc[1][0]);
                acc[1][1] = f2_fma(b2, v2.y, acc[1][1]);
                acc[0][0] = f2_fma(a3, v3.x, acc[0][0]);
                acc[0][1] = f2_fma(a3, v3.y, acc[0][1]);
                acc[1][0] = f2_fma(b3, v3.x, acc[1][0]);
                acc[1][1] = f2_fma(b3, v3.y, acc[1][1]);
                lp[0] += (PA.x + PA.y) + (PA.z + PA.w);
                lp[1] += (PB.x + PB.y) + (PB.z + PB.w);
            }
        }
        __syncwarp();
    }

    // ---- direct store ----
    #pragma unroll
    for (int oct = 0; oct < 2; oct++) {
        const int i = oct * 8 + io;
        float a0, a1, a2, a3;
        f2_unpack(acc[oct][0], a0, a1);
        f2_unpack(acc[oct][1], a2, a3);
        *(float4*)&g_part[((size_t)(i0 + i) * NSPLIT + blockIdx.y) * DM + h * DH + dq * 4] =
            make_float4(a0, a1, a2, a3);
        if (dq == 0)
            g_lsum[((i0 + i) * NSPLIT + blockIdx.y) * HH + h] = lp[oct];
    }
}

// ---------- kernel 3: combine partials + normalize + @ Wo (256 thr, 4 rows, grid 512) ----------
__global__ __launch_bounds__(256)
void combine_kernel(const float* __restrict__ Wo, float* __restrict__ out) {
    __shared__ float xs[4][DM];
    __shared__ float ws[PCH][DM];
    const int i0 = blockIdx.x * 4;
    const int tid = threadIdx.x;
    const int c = tid & 127;
    const int rh = tid >> 7;           // rows {0,1} or {2,3}
    const int h = c >> 4;
    #pragma unroll
    for (int r = 0; r < 2; r++) {
        int i = i0 + rh * 2 + r;
        float s = 0.f, l = 0.f;
        #pragma unroll
        for (int sp = 0; sp < NSPLIT; sp++) {
            s += g_part[((size_t)i * NSPLIT + sp) * DM + c];
            l += g_lsum[(i * NSPLIT + sp) * HH + h];
        }
        xs[rh * 2 + r][c] = s / l;
    }
    float a[2] = {0.f, 0.f};
    for (int ch = 0; ch < DM / PCH; ch++) {
        const int d0 = ch * PCH;
        __syncthreads();
        #pragma unroll
        for (int s = 0; s < 2; s++) {
            int t = tid + s * 256;
            int dd = t >> 5, c4 = t & 31;
            *(float4*)&ws[dd][c4 * 4] = *(const float4*)&Wo[(d0 + dd) * DM + c4 * 4];
        }
        __syncthreads();
        #pragma unroll
        for (int dd = 0; dd < PCH; dd++) {
            float wv = ws[dd][c];
            a[0] += xs[rh * 2 + 0][d0 + dd] * wv;
            a[1] += xs[rh * 2 + 1][d0 + dd] * wv;
        }
    }
    out[(i0 + rh * 2 + 0) * DM + c] = a[0];
    out[(i0 + rh * 2 + 1) * DM + c] = a[1];
}

// ---------- launch ----------
extern "C" void kernel_launch(void* const* d_in, const int* in_sizes, int n_in,
                              void* d_out, int out_size) {
    const float* X    = (const float*)d_in[0];
    const int*   adj  = (const int*)  d_in[1];
    const float* edge = (const float*)d_in[2];
    const float* Wq   = (const float*)d_in[3];
    const float* Wk   = (const float*)d_in[4];
    const float* Wv   = (const float*)d_in[5];
    const float* We   = (const float*)d_in[6];
    const float* Wr   = (const float*)d_in[7];
    const float* Wo   = (const float*)d_in[8];
    float* out = (float*)d_out;

    const int smem_bytes = (HH*BI*SCSTR + 32*VSTR4*4 + BI*JT_PER) * 4;
    cudaFuncSetAttribute(attn_kernel, cudaFuncAttributeMaxDynamicSharedMemorySize, smem_bytes);

    proj_kernel<<<NN / 16, 512>>>(X, Wq, Wk, Wv, We, Wr);
    attn_kernel<<<dim3(NN / BI, NSPLIT), 256, smem_bytes>>>(adj, edge);
    combine_kernel<<<NN / 4, 256>>>(Wo, out);
}